// round 16
// baseline (speedup 1.0000x reference)
#include <cuda_runtime.h>
#include <math.h>

// Phase 1 + gridbar: byte-identical to R15 (passing @27.1us).
// Post-barrier: ONE phase only — 8 blocks (one per head) compute M by
// streaming phi_k/u in 128-token chunks (no Mpart global round-trip,
// no second barrier), then the full epilogue for that head.

#define G 144
#define T 1024

__device__ __align__(16) float g_f[2][4096];
__device__ __align__(16) float g_phi[2][4096*32];
__device__ __align__(16) float g_u[4096*32];
__device__ unsigned g_mg_ord[8];
__device__ unsigned g_m2_ord[8*32];
__device__ unsigned long long g_bar;

__device__ __forceinline__ float softplusf(float x){
    return x > 20.0f ? x : __logf(1.0f + __expf(x));
}
__device__ __forceinline__ unsigned ordf(float f){
    unsigned u = __float_as_uint(f);
    return (u & 0x80000000u) ? ~u : (u | 0x80000000u);
}
__device__ __forceinline__ float deco(unsigned k){
    return __uint_as_float((k & 0x80000000u) ? (k ^ 0x80000000u) : ~k);
}

__device__ __forceinline__ unsigned long long pk2(float a){
    unsigned long long r;
    asm("mov.b64 %0, {%1, %1};" : "=l"(r) : "f"(a));
    return r;
}
__device__ __forceinline__ void fma2(unsigned long long &acc,
                                     unsigned long long a, unsigned long long b){
    asm("fma.rn.f32x2 %0, %1, %2, %0;" : "+l"(acc) : "l"(a), "l"(b));
}
__device__ __forceinline__ void up2(unsigned long long v, float &lo, float &hi){
    asm("mov.b64 {%0, %1}, %2;" : "=f"(lo), "=f"(hi) : "l"(v));
}

__device__ __forceinline__ void gridbar(){
    __syncthreads();
    if (threadIdx.x == 0){
        __threadfence();
        unsigned long long t = atomicAdd(&g_bar, 1ULL);
        unsigned long long target = (t / G + 1ULL) * G;
        unsigned ns = 32;
        while (*((volatile unsigned long long*)&g_bar) < target){
            __nanosleep(ns);
            if (ns < 256) ns <<= 1;
        }
        __threadfence();
    }
    __syncthreads();
}

// ---- shared layout (floats) ----
// ICNN blocks:
#define O_W1   0        // 64x65
#define O_W2   4160     // 64x65
#define O_WHT  8320     // 64x32  [d][r]
#define O_X    10368    // 64x64  [t][d]
#define O_XT   14464    // 64x68  [d][t]
#define O_Z1T  18816    // 64x68
#define O_B1   23168
#define O_B2   23232
#define O_RED  23296    // 128
// u-blocks:
#define O_UWVT 0        // 64x32 [d][p]
#define O_SVT  2048     // 64x264 [d][t]
#define O_URED 18944    // 1024
// final head-blocks:
#define FB_SEG 0        // 512
#define FB_SF  512      // 512
#define FB_M2  1024     // 32
#define FB_M   1056     // 1024
#define FB_A   2080     // 4096 chunk phik  (reused as spq half: 8192)
#define FB_B   6176     // 4096 chunk w
#define SMEM_FLOATS 23424

__global__ void __launch_bounds__(T, 1) fused_kernel(
    const float* __restrict__ q,  const float* __restrict__ k,  const float* __restrict__ v,
    const float* __restrict__ sq1, const float* __restrict__ sqb1,
    const float* __restrict__ sq2, const float* __restrict__ sqb2,
    const float* __restrict__ sk1, const float* __restrict__ skb1,
    const float* __restrict__ sk2, const float* __restrict__ skb2,
    const float* __restrict__ Wh, const float* __restrict__ Wv,
    float* __restrict__ y)
{
    extern __shared__ __align__(16) float S[];
    const int tid = threadIdx.x;
    const int bid = blockIdx.x;

    // ============================ PHASE 1 (verbatim R15) ============================
    if (bid < 128){
        const int which = (bid >= 64);
        const float* x    = which ? k   : q;
        const float* raw1 = which ? sk1 : sq1;
        const float* raw2 = which ? sk2 : sq2;
        const float* b1   = which ? skb1: sqb1;
        const float* b2   = which ? skb2: sqb2;
        const int tb = (which ? bid - 64 : bid) * 64;
        const int h  = tb >> 9;

        float* sW1  = S + O_W1;
        float* sW2  = S + O_W2;
        float* sWhT = S + O_WHT;
        float* sx   = S + O_X;
        float* sxT  = S + O_XT;
        float* sz1T = S + O_Z1T;
        float* sb1  = S + O_B1;
        float* sb2  = S + O_B2;
        float* sred = S + O_RED;

        for (int i = tid; i < 4096; i += T){
            int j = i >> 6, d = i & 63;
            sW1[j*65 + d] = softplusf(raw1[i]);
            sW2[j*65 + d] = softplusf(raw2[i]);
        }
        for (int i = tid; i < 2048; i += T){
            int r = i >> 6, d = i & 63;
            sWhT[d*32 + r] = Wh[i];
        }
        for (int i = tid; i < 4096; i += T){
            int t = i >> 6, d = i & 63;
            float val = x[tb*64 + i];
            sx[i] = val;
            sxT[d*68 + t] = val;
        }
        if (tid < 64){ sb1[tid] = b1[tid]; sb2[tid] = b2[tid]; }
        __syncthreads();

        const int grp = tid >> 6;     // 0..15, 4 tokens each
        const int j   = tid & 63;
        const int t0  = grp * 4;

        {   // layer 1
            unsigned long long a0, a1;
            a0 = a1 = pk2(sb1[j]);
            #pragma unroll 16
            for (int d = 0; d < 64; d++){
                unsigned long long ww = pk2(sW1[j*65 + d]);
                ulonglong2 xa = *(const ulonglong2*)&sxT[d*68 + t0];
                fma2(a0, xa.x, ww); fma2(a1, xa.y, ww);
            }
            float z[4];
            up2(a0, z[0], z[1]); up2(a1, z[2], z[3]);
            #pragma unroll
            for (int i = 0; i < 4; i++) z[i] = softplusf(z[i]);
            unsigned long long s1x, s1y;
            asm("mov.b64 %0, {%1, %2};" : "=l"(s1x) : "f"(z[0]), "f"(z[1]));
            asm("mov.b64 %0, {%1, %2};" : "=l"(s1y) : "f"(z[2]), "f"(z[3]));
            ulonglong2 s1; s1.x = s1x; s1.y = s1y;
            *(ulonglong2*)&sz1T[j*68 + t0] = s1;
        }
        __syncthreads();

        {   // layer 2 + reduce over j
            unsigned long long a0, a1;
            a0 = a1 = pk2(sb2[j]);
            #pragma unroll 16
            for (int d = 0; d < 64; d++){
                unsigned long long ww = pk2(sW2[j*65 + d]);
                ulonglong2 xa = *(const ulonglong2*)&sz1T[d*68 + t0];
                fma2(a0, xa.x, ww); fma2(a1, xa.y, ww);
            }
            float cv[4];
            up2(a0, cv[0], cv[1]); up2(a1, cv[2], cv[3]);
            #pragma unroll
            for (int i = 0; i < 4; i++){
                float cc2 = softplusf(cv[i]);
                #pragma unroll
                for (int o = 16; o > 0; o >>= 1)
                    cc2 += __shfl_xor_sync(0xffffffffu, cc2, o);
                cv[i] = cc2;
            }
            if ((tid & 31) == 0){
                int w = tid >> 5;   // 0..31
                #pragma unroll
                for (int i = 0; i < 4; i++) sred[w*4 + i] = cv[i];
            }
        }
        __syncthreads();

        if (tid < 64){
            int t = tid, g2 = t >> 2, i2 = t & 3;
            float f = sred[(g2*2)*4 + i2] + sred[(g2*2 + 1)*4 + i2];
            g_f[which][tb + t] = f;
            if (which){
                float m = f;
                #pragma unroll
                for (int o = 16; o > 0; o >>= 1)
                    m = fmaxf(m, __shfl_xor_sync(0xffffffffu, m, o));
                if ((tid & 31) == 0) atomicMax(&g_mg_ord[h], ordf(m));
            }
        }

        {   // phi: thread = (token, 2 r's)
            const int pt = tid >> 4;          // 0..63
            const int r0 = (tid & 15) * 2;
            unsigned long long p01 = 0ULL;
            #pragma unroll 8
            for (int d4 = 0; d4 < 64; d4 += 4){
                float4 xq = *(const float4*)&sx[pt*64 + d4];
                { unsigned long long wp = *(const unsigned long long*)&sWhT[(d4  )*32 + r0];
                  fma2(p01, pk2(xq.x), wp); }
                { unsigned long long wp = *(const unsigned long long*)&sWhT[(d4+1)*32 + r0];
                  fma2(p01, pk2(xq.y), wp); }
                { unsigned long long wp = *(const unsigned long long*)&sWhT[(d4+2)*32 + r0];
                  fma2(p01, pk2(xq.z), wp); }
                { unsigned long long wp = *(const unsigned long long*)&sWhT[(d4+3)*32 + r0];
                  fma2(p01, pk2(xq.w), wp); }
            }
            float e0, e1;
            up2(p01, e0, e1);
            int base = (tb + pt)*32 + r0;
            g_phi[which][base + 0] = __expf(e0);
            g_phi[which][base + 1] = __expf(e1);
        }
    } else {
        // ---- u = v @ Wv.T, blocks 128..143, 256 tokens each (verbatim R15) ----
        const int ub = bid - 128;
        const int tb = ub * 256;
        const int h  = tb >> 9;
        float* sWvT = S + O_UWVT;
        float* svT  = S + O_SVT;       // [d][t] stride 264
        float* sred = S + O_URED;      // 32x32

        for (int i = tid; i < 2048; i += T){
            int r = i >> 6, d = i & 63;
            sWvT[d*32 + r] = Wv[i];
        }
        for (int i = tid; i < 16384; i += T){
            int t = i >> 6, d = i & 63;
            svT[d*264 + t] = v[tb*64 + i];
        }
        __syncthreads();

        const int p = tid & 31, tr = tid >> 5;   // 32 tr, 8 tokens each
        const int t0 = tr*8;
        unsigned long long a0=0,a1=0,a2=0,a3=0;
        #pragma unroll 8
        for (int d = 0; d < 64; d++){
            unsigned long long ww = pk2(sWvT[d*32 + p]);
            const float* row = &svT[d*264];
            ulonglong2 xa = *(const ulonglong2*)&row[t0];
            ulonglong2 xb = *(const ulonglong2*)&row[t0 + 4];
            fma2(a0, xa.x, ww); fma2(a1, xa.y, ww);
            fma2(a2, xb.x, ww); fma2(a3, xb.y, ww);
        }
        float uv[8];
        up2(a0, uv[0], uv[1]); up2(a1, uv[2], uv[3]);
        up2(a2, uv[4], uv[5]); up2(a3, uv[6], uv[7]);
        float mx = -1e30f;
        #pragma unroll
        for (int i = 0; i < 8; i++){
            g_u[(tb + t0 + i)*32 + p] = uv[i];
            mx = fmaxf(mx, uv[i]);
        }
        sred[tr*32 + p] = mx;
        __syncthreads();
        if (tid < 32){
            float m = sred[tid];
            #pragma unroll
            for (int rr = 1; rr < 32; rr++) m = fmaxf(m, sred[rr*32 + tid]);
            atomicMax(&g_m2_ord[h*32 + tid], ordf(m));
        }
    }

    gridbar();

    // ================= FINAL PHASE: 8 head-blocks, no 2nd barrier =================
    if (bid < 8){
        const int h = bid;
        float* seg = S + FB_SEG;   // 512
        float* sf  = S + FB_SF;    // 512
        float* sm2 = S + FB_M2;    // 32
        float* sM  = S + FB_M;     // 1024
        float* sA  = S + FB_A;     // 4096 (phik chunk / spq half)
        float* sB  = S + FB_B;     // 4096 (w chunk)

        const float mg = deco(__ldcg(&g_mg_ord[h]));
        if (tid < 32) sm2[tid] = deco(__ldcg(&g_m2_ord[h*32 + tid]));
        if (tid < 512){
            seg[tid] = __expf(__ldcg(&g_f[1][h*512 + tid]) - mg);
            sf[tid]  = __ldcg(&g_f[0][h*512 + tid]);
        }
        if (tid < 1024) sM[tid] = 0.f;
        __syncthreads();

        // M[r,p] accumulated over 4 chunks of 128 tokens
        const int r = tid >> 5, p = tid & 31;
        float macc = 0.f;
        for (int cc = 0; cc < 4; cc++){
            const int ct = h*512 + cc*128;      // global token base
            for (int i = tid; i < 4096; i += T){
                int t = i >> 5, pp = i & 31;
                sA[i] = __ldcg(&g_phi[1][(ct + t)*32 + pp]);
                sB[i] = seg[cc*128 + t] * __expf(__ldcg(&g_u[(ct + t)*32 + pp]) - sm2[pp]);
            }
            __syncthreads();
            #pragma unroll 16
            for (int t = 0; t < 128; t++)
                macc += sA[t*32 + r] * sB[t*32 + p];
            __syncthreads();
        }
        sM[r*32 + p] = macc;
        __syncthreads();

        // Epilogue: 2 halves of 256 s; spq streamed into sA/sB (8192 floats)
        const float LOGS = 6.2383246250395077847f;  // log(512)
        float* spq = sA;                            // 8192 contiguous (FB_A..FB_A+8192)
        for (int half = 0; half < 2; half++){
            const int sbase = h*512 + half*256;
            for (int i = tid; i < 8192; i += T)
                spq[i] = __ldcg(&g_phi[0][sbase*32 + i]);
            __syncthreads();
            #pragma unroll
            for (int io = 0; io < 8; io++){
                int o = tid + io*1024;              // 0..8191
                int sl = o >> 5, pp = o & 31;
                float a = 0.f;
                #pragma unroll
                for (int rr = 0; rr < 32; rr++)
                    a += spq[sl*32 + rr] * sM[rr*32 + pp];
                y[(sbase + sl)*32 + pp] =
                    sf[half*256 + sl] + mg + sm2[pp] - LOGS + __logf(a);
            }
            __syncthreads();
        }
    }
}

extern "C" void kernel_launch(void* const* d_in, const int* in_sizes, int n_in,
                              void* d_out, int out_size){
    const float* q    = (const float*)d_in[0];
    const float* k    = (const float*)d_in[1];
    const float* v    = (const float*)d_in[2];
    const float* sq1  = (const float*)d_in[3];
    const float* sqb1 = (const float*)d_in[4];
    const float* sq2  = (const float*)d_in[5];
    const float* sqb2 = (const float*)d_in[6];
    const float* sk1  = (const float*)d_in[7];
    const float* skb1 = (const float*)d_in[8];
    const float* sk2  = (const float*)d_in[9];
    const float* skb2 = (const float*)d_in[10];
    const float* Wh   = (const float*)d_in[11];
    const float* Wv   = (const float*)d_in[12];
    float* y = (float*)d_out;

    cudaFuncSetAttribute(fused_kernel, cudaFuncAttributeMaxDynamicSharedMemorySize,
                         SMEM_FLOATS * (int)sizeof(float));
    fused_kernel<<<G, T, SMEM_FLOATS * sizeof(float)>>>(
        q, k, v, sq1, sqb1, sq2, sqb2, sk1, skb1, sk2, skb2, Wh, Wv, y);
}

// round 17
// speedup vs baseline: 1.9374x; 1.9374x over previous
#include <cuda_runtime.h>
#include <math.h>

// R15 base (champion @27.1us). Changes:
//  1) Phase-1 warp specialization: warps 0-15 run ICNN (R8's proven 8-tok/thread
//     bodies, internal bar.sync id=1 on 512 threads); warps 16-31 run phi
//     concurrently (R8's proven 4-r/thread body).
//  2) Phase 2/3 global reads of my own 16B-aligned arrays via float4 __ldcg
//     (pattern proven passing in R2).

#define G 144
#define T 1024

__device__ __align__(16) float g_f[2][4096];
__device__ __align__(16) float g_phi[2][4096*32];
__device__ __align__(16) float g_u[4096*32];
__device__ __align__(16) float g_Mpart[64][1024];
__device__ unsigned g_mg_ord[8];
__device__ unsigned g_m2_ord[8*32];
__device__ unsigned long long g_bar;

__device__ __forceinline__ float softplusf(float x){
    return x > 20.0f ? x : __logf(1.0f + __expf(x));
}
__device__ __forceinline__ unsigned ordf(float f){
    unsigned u = __float_as_uint(f);
    return (u & 0x80000000u) ? ~u : (u | 0x80000000u);
}
__device__ __forceinline__ float deco(unsigned k){
    return __uint_as_float((k & 0x80000000u) ? (k ^ 0x80000000u) : ~k);
}

__device__ __forceinline__ unsigned long long pk2(float a){
    unsigned long long r;
    asm("mov.b64 %0, {%1, %1};" : "=l"(r) : "f"(a));
    return r;
}
__device__ __forceinline__ unsigned long long pkpair(float lo, float hi){
    unsigned long long r;
    asm("mov.b64 %0, {%1, %2};" : "=l"(r) : "f"(lo), "f"(hi));
    return r;
}
__device__ __forceinline__ void fma2(unsigned long long &acc,
                                     unsigned long long a, unsigned long long b){
    asm("fma.rn.f32x2 %0, %1, %2, %0;" : "+l"(acc) : "l"(a), "l"(b));
}
__device__ __forceinline__ void up2(unsigned long long v, float &lo, float &hi){
    asm("mov.b64 {%0, %1}, %2;" : "=f"(lo), "=f"(hi) : "l"(v));
}

__device__ __forceinline__ void gridbar(){
    __syncthreads();
    if (threadIdx.x == 0){
        __threadfence();
        unsigned long long t = atomicAdd(&g_bar, 1ULL);
        unsigned long long target = (t / G + 1ULL) * G;
        unsigned ns = 32;
        while (*((volatile unsigned long long*)&g_bar) < target){
            __nanosleep(ns);
            if (ns < 256) ns <<= 1;
        }
        __threadfence();
    }
    __syncthreads();
}

// ---- shared layout (floats) ----
// ICNN blocks:
#define O_W1   0        // 64x65
#define O_W2   4160     // 64x65
#define O_WHT  8320     // 64x32  [d][r]
#define O_X    10368    // 64x64  [t][d]
#define O_XT   14464    // 64x68  [d][t]
#define O_Z1T  18816    // 64x68
#define O_B1   23168
#define O_B2   23232
#define O_RED  23296    // 128
// u-blocks:
#define O_UWVT 0        // 64x32 [d][p]
#define O_SVT  2048     // 64x264 [d][t]
#define O_URED 18944    // 1024
#define SMEM_FLOATS 23424

__global__ void __launch_bounds__(T, 1) fused_kernel(
    const float* __restrict__ q,  const float* __restrict__ k,  const float* __restrict__ v,
    const float* __restrict__ sq1, const float* __restrict__ sqb1,
    const float* __restrict__ sq2, const float* __restrict__ sqb2,
    const float* __restrict__ sk1, const float* __restrict__ skb1,
    const float* __restrict__ sk2, const float* __restrict__ skb2,
    const float* __restrict__ Wh, const float* __restrict__ Wv,
    float* __restrict__ y)
{
    extern __shared__ __align__(16) float S[];
    const int tid = threadIdx.x;
    const int bid = blockIdx.x;

    // ============================ PHASE 1 ============================
    if (bid < 128){
        const int which = (bid >= 64);
        const float* x    = which ? k   : q;
        const float* raw1 = which ? sk1 : sq1;
        const float* raw2 = which ? sk2 : sq2;
        const float* b1   = which ? skb1: sqb1;
        const float* b2   = which ? skb2: sqb2;
        const int tb = (which ? bid - 64 : bid) * 64;
        const int h  = tb >> 9;

        float* sW1  = S + O_W1;
        float* sW2  = S + O_W2;
        float* sWhT = S + O_WHT;
        float* sx   = S + O_X;
        float* sxT  = S + O_XT;
        float* sz1T = S + O_Z1T;
        float* sb1  = S + O_B1;
        float* sb2  = S + O_B2;
        float* sred = S + O_RED;

        // ---------------- preamble (all 1024 threads, verbatim R15) ----------------
        for (int i = tid; i < 4096; i += T){
            int j = i >> 6, d = i & 63;
            sW1[j*65 + d] = softplusf(raw1[i]);
            sW2[j*65 + d] = softplusf(raw2[i]);
        }
        for (int i = tid; i < 2048; i += T){
            int r = i >> 6, d = i & 63;
            sWhT[d*32 + r] = Wh[i];
        }
        for (int i = tid; i < 4096; i += T){
            int t = i >> 6, d = i & 63;
            float val = x[tb*64 + i];
            sx[i] = val;
            sxT[d*68 + t] = val;
        }
        if (tid < 64){ sb1[tid] = b1[tid]; sb2[tid] = b2[tid]; }
        __syncthreads();

        if (tid < 512){
            // ============ ICNN half (R8's proven 8-tok/thread bodies) ============
            const int grp = tid >> 6;     // 0..7, 8 tokens each
            const int j   = tid & 63;
            const int t0  = grp * 8;

            {   // layer 1
                unsigned long long a0, a1, a2, a3;
                a0 = a1 = a2 = a3 = pk2(sb1[j]);
                #pragma unroll 16
                for (int d = 0; d < 64; d++){
                    unsigned long long ww = pk2(sW1[j*65 + d]);
                    ulonglong2 xa = *(const ulonglong2*)&sxT[d*68 + t0];
                    ulonglong2 xb = *(const ulonglong2*)&sxT[d*68 + t0 + 4];
                    fma2(a0, xa.x, ww); fma2(a1, xa.y, ww);
                    fma2(a2, xb.x, ww); fma2(a3, xb.y, ww);
                }
                float z[8];
                up2(a0, z[0], z[1]); up2(a1, z[2], z[3]);
                up2(a2, z[4], z[5]); up2(a3, z[6], z[7]);
                #pragma unroll
                for (int i = 0; i < 8; i++) z[i] = softplusf(z[i]);
                ulonglong2 s1, s2;
                s1.x = pkpair(z[0], z[1]); s1.y = pkpair(z[2], z[3]);
                s2.x = pkpair(z[4], z[5]); s2.y = pkpair(z[6], z[7]);
                *(ulonglong2*)&sz1T[j*68 + t0]     = s1;
                *(ulonglong2*)&sz1T[j*68 + t0 + 4] = s2;
            }
            asm volatile("bar.sync 1, 512;" ::: "memory");

            {   // layer 2 + reduce over j
                unsigned long long a0, a1, a2, a3;
                a0 = a1 = a2 = a3 = pk2(sb2[j]);
                #pragma unroll 16
                for (int d = 0; d < 64; d++){
                    unsigned long long ww = pk2(sW2[j*65 + d]);
                    ulonglong2 xa = *(const ulonglong2*)&sz1T[d*68 + t0];
                    ulonglong2 xb = *(const ulonglong2*)&sz1T[d*68 + t0 + 4];
                    fma2(a0, xa.x, ww); fma2(a1, xa.y, ww);
                    fma2(a2, xb.x, ww); fma2(a3, xb.y, ww);
                }
                float cv[8];
                up2(a0, cv[0], cv[1]); up2(a1, cv[2], cv[3]);
                up2(a2, cv[4], cv[5]); up2(a3, cv[6], cv[7]);
                #pragma unroll
                for (int i = 0; i < 8; i++){
                    float c = softplusf(cv[i]);
                    #pragma unroll
                    for (int o = 16; o > 0; o >>= 1)
                        c += __shfl_xor_sync(0xffffffffu, c, o);
                    cv[i] = c;
                }
                if ((tid & 31) == 0){
                    int w = tid >> 5;   // warp 0..15
                    #pragma unroll
                    for (int i = 0; i < 8; i++) sred[w*8 + i] = cv[i];
                }
            }
            asm volatile("bar.sync 1, 512;" ::: "memory");

            if (tid < 64){
                int t = tid, g2 = t >> 3, i2 = t & 7;
                float f = sred[(g2*2)*8 + i2] + sred[(g2*2 + 1)*8 + i2];
                g_f[which][tb + t] = f;
                if (which){
                    float m = f;
                    #pragma unroll
                    for (int o = 16; o > 0; o >>= 1)
                        m = fmaxf(m, __shfl_xor_sync(0xffffffffu, m, o));
                    if ((tid & 31) == 0) atomicMax(&g_mg_ord[h], ordf(m));
                }
            }
        } else {
            // ============ phi half (R8's proven 4-r/thread body) ============
            const int wg = tid - 512;         // 0..511
            const int pt = wg >> 3;           // 0..63
            const int r0 = (wg & 7) * 4;
            unsigned long long p01 = 0ULL, p23 = 0ULL;
            #pragma unroll 8
            for (int d4 = 0; d4 < 64; d4 += 4){
                float4 xq = *(const float4*)&sx[pt*64 + d4];
                {
                    ulonglong2 wp = *(const ulonglong2*)&sWhT[(d4  )*32 + r0];
                    unsigned long long xx = pk2(xq.x);
                    fma2(p01, xx, wp.x); fma2(p23, xx, wp.y);
                }
                {
                    ulonglong2 wp = *(const ulonglong2*)&sWhT[(d4+1)*32 + r0];
                    unsigned long long xx = pk2(xq.y);
                    fma2(p01, xx, wp.x); fma2(p23, xx, wp.y);
                }
                {
                    ulonglong2 wp = *(const ulonglong2*)&sWhT[(d4+2)*32 + r0];
                    unsigned long long xx = pk2(xq.z);
                    fma2(p01, xx, wp.x); fma2(p23, xx, wp.y);
                }
                {
                    ulonglong2 wp = *(const ulonglong2*)&sWhT[(d4+3)*32 + r0];
                    unsigned long long xx = pk2(xq.w);
                    fma2(p01, xx, wp.x); fma2(p23, xx, wp.y);
                }
            }
            float e0, e1, e2, e3;
            up2(p01, e0, e1); up2(p23, e2, e3);
            int base = (tb + pt)*32 + r0;
            g_phi[which][base + 0] = __expf(e0);
            g_phi[which][base + 1] = __expf(e1);
            g_phi[which][base + 2] = __expf(e2);
            g_phi[which][base + 3] = __expf(e3);
        }
    } else {
        // ---- u = v @ Wv.T, blocks 128..143, 256 tokens each (verbatim R15) ----
        const int ub = bid - 128;
        const int tb = ub * 256;
        const int h  = tb >> 9;
        float* sWvT = S + O_UWVT;
        float* svT  = S + O_SVT;       // [d][t] stride 264
        float* sred = S + O_URED;      // 32x32

        for (int i = tid; i < 2048; i += T){
            int r = i >> 6, d = i & 63;
            sWvT[d*32 + r] = Wv[i];
        }
        for (int i = tid; i < 16384; i += T){
            int t = i >> 6, d = i & 63;
            svT[d*264 + t] = v[tb*64 + i];
        }
        __syncthreads();

        const int p = tid & 31, tr = tid >> 5;   // 32 tr, 8 tokens each
        const int t0 = tr*8;
        unsigned long long a0=0,a1=0,a2=0,a3=0;
        #pragma unroll 8
        for (int d = 0; d < 64; d++){
            unsigned long long ww = pk2(sWvT[d*32 + p]);
            const float* row = &svT[d*264];
            ulonglong2 xa = *(const ulonglong2*)&row[t0];
            ulonglong2 xb = *(const ulonglong2*)&row[t0 + 4];
            fma2(a0, xa.x, ww); fma2(a1, xa.y, ww);
            fma2(a2, xb.x, ww); fma2(a3, xb.y, ww);
        }
        float uv[8];
        up2(a0, uv[0], uv[1]); up2(a1, uv[2], uv[3]);
        up2(a2, uv[4], uv[5]); up2(a3, uv[6], uv[7]);
        float mx = -1e30f;
        #pragma unroll
        for (int i = 0; i < 8; i++){
            g_u[(tb + t0 + i)*32 + p] = uv[i];
            mx = fmaxf(mx, uv[i]);
        }
        sred[tr*32 + p] = mx;
        __syncthreads();
        if (tid < 32){
            float m = sred[tid];
            #pragma unroll
            for (int rr = 1; rr < 32; rr++) m = fmaxf(m, sred[rr*32 + tid]);
            atomicMax(&g_m2_ord[h*32 + tid], ordf(m));
        }
    }

    gridbar();

    // ============================ PHASE 2 ============================
    if (bid < 64){
        const int h = bid >> 3, c = bid & 7;
        const int gtb = h*512 + c*64;
        float* seg = S;          // 64
        float* sm2 = S + 64;     // 32
        float* sw  = S + 96;     // 64x32
        float* spk = S + 96 + 2048; // 64x32  (O_W? ok — 16B aligned: 96*4=384... NOT 16B? 96 floats = 384B, aligned 16 ✓; spk at (96+2048)*4 ✓)

        float mg = deco(__ldcg(&g_mg_ord[h]));
        if (tid < 32) sm2[tid] = deco(__ldcg(&g_m2_ord[h*32 + tid]));
        if (tid >= 64 && tid < 128) seg[tid - 64] = __expf(__ldcg(&g_f[1][gtb + tid - 64]) - mg);
        __syncthreads();

        // float4 loads of my own aligned arrays (R2-proven pattern)
        if (tid < 512){
            float4 pk4 = __ldcg((const float4*)&g_phi[1][gtb*32] + tid);
            *(float4*)&spk[tid*4] = pk4;
            float4 u4 = __ldcg((const float4*)&g_u[gtb*32] + tid);
            int t = tid >> 3, p0 = (tid & 7) * 4;
            float sg = seg[t];
            float4 w4;
            w4.x = sg * __expf(u4.x - sm2[p0    ]);
            w4.y = sg * __expf(u4.y - sm2[p0 + 1]);
            w4.z = sg * __expf(u4.z - sm2[p0 + 2]);
            w4.w = sg * __expf(u4.w - sm2[p0 + 3]);
            *(float4*)&sw[tid*4] = w4;
        }
        __syncthreads();

        if (tid < 1024){
            int r = tid >> 5, p = tid & 31;
            float a = 0.f;
            #pragma unroll
            for (int t = 0; t < 64; t++) a += spk[t*32 + r] * sw[t*32 + p];
            g_Mpart[bid][tid] = a;
        }
    }

    gridbar();

    // ============================ PHASE 3 ============================
    if (bid < 128){
        const int h = bid >> 4, sc = bid & 15;
        const int s0 = h*512 + sc*32;
        float* sM  = S;          // 32x32
        float* spq = S + 1024;   // 32x32
        float* sm2 = S + 2048;   // 32
        float* sf  = S + 2080;   // 32

        if (tid < 256){
            float4 a4 = make_float4(0.f, 0.f, 0.f, 0.f);
            #pragma unroll
            for (int c = 0; c < 8; c++){
                float4 m4 = __ldcg((const float4*)&g_Mpart[h*8 + c][0] + tid);
                a4.x += m4.x; a4.y += m4.y; a4.z += m4.z; a4.w += m4.w;
            }
            *(float4*)&sM[tid*4] = a4;
            *(float4*)&spq[tid*4] = __ldcg((const float4*)&g_phi[0][s0*32] + tid);
        }
        if (tid >= 256 && tid < 288) sm2[tid - 256] = deco(__ldcg(&g_m2_ord[h*32 + tid - 256]));
        if (tid >= 288 && tid < 320) sf[tid - 288]  = __ldcg(&g_f[0][s0 + tid - 288]);
        float mg = deco(__ldcg(&g_mg_ord[h]));
        __syncthreads();

        const float LOGS = 6.2383246250395077847f; // log(512)
        if (tid < 1024){
            int s = tid >> 5, p = tid & 31;
            float a = 0.f;
            #pragma unroll
            for (int r = 0; r < 32; r++) a += spq[s*32 + r] * sM[r*32 + p];
            y[(s0 + s)*32 + p] = sf[s] + mg + sm2[p] - LOGS + __logf(a);
        }
    }
}

extern "C" void kernel_launch(void* const* d_in, const int* in_sizes, int n_in,
                              void* d_out, int out_size){
    const float* q    = (const float*)d_in[0];
    const float* k    = (const float*)d_in[1];
    const float* v    = (const float*)d_in[2];
    const float* sq1  = (const float*)d_in[3];
    const float* sqb1 = (const float*)d_in[4];
    const float* sq2  = (const float*)d_in[5];
    const float* sqb2 = (const float*)d_in[6];
    const float* sk1  = (const float*)d_in[7];
    const float* skb1 = (const float*)d_in[8];
    const float* sk2  = (const float*)d_in[9];
    const float* skb2 = (const float*)d_in[10];
    const float* Wh   = (const float*)d_in[11];
    const float* Wv   = (const float*)d_in[12];
    float* y = (float*)d_out;

    cudaFuncSetAttribute(fused_kernel, cudaFuncAttributeMaxDynamicSharedMemorySize,
                         SMEM_FLOATS * (int)sizeof(float));
    fused_kernel<<<G, T, SMEM_FLOATS * sizeof(float)>>>(
        q, k, v, sq1, sqb1, sq2, sqb2, sk1, skb1, sk2, skb2, Wh, Wv, y);
}